// round 13
// baseline (speedup 1.0000x reference)
#include <cuda_runtime.h>
#include <math.h>

// Problem constants
#define B_  16
#define NN  4096
#define D_  64
#define O_  12
#define S_  32
#define M_  12
#define A_  32

// Output layout: H_time [B,O,N,D] ++ attn [B,O,N,M] ++ gate [B,O,M]
#define ATT_OFF  50331648ull
#define GATE_OFF 59768832ull
#define SCALE 0.17677669529663688f   // 1/sqrt(32)

#define QSTRIDE 36   // qh row stride in floats: 9x16B -> LDS.128-aligned, conflict-free

// Scratch
__device__ float g_key[B_*O_*A_*M_];      // [b][o][a][m]
__device__ float g_val[B_*O_*M_*D_];      // [b][o][m][d]  (gate folded in)
__device__ float g_c  [B_*O_*M_];         // [b][o][m]     (qs . key)

typedef unsigned long long ull;

__device__ __forceinline__ ull ffma2(ull a, ull b, ull c) {
    ull d;
    asm("fma.rn.f32x2 %0, %1, %2, %3;" : "=l"(d) : "l"(a), "l"(b), "l"(c));
    return d;
}
__device__ __forceinline__ ull pack2(float x, float y) {
    ull r;
    asm("mov.b64 %0, {%1, %2};" : "=l"(r) : "r"(__float_as_uint(x)), "r"(__float_as_uint(y)));
    return r;
}
__device__ __forceinline__ float2 unpack2(ull v) {
    unsigned int lo, hi;
    asm("mov.b64 {%0, %1}, %2;" : "=r"(lo), "=r"(hi) : "l"(v));
    return make_float2(__uint_as_float(lo), __uint_as_float(hi));
}

// ============================================================================
// Kernel 1: precompute for one (b, o) per block (tiny; ~2-3 us total)
// ============================================================================
__global__ __launch_bounds__(128)
void precompute_kernel(const float* __restrict__ ts_out,
                       const float* __restrict__ step_emb,
                       const float* __restrict__ key_emb,
                       const float* __restrict__ val_emb,
                       const float* __restrict__ Wk,
                       const float* __restrict__ Wg,
                       const float* __restrict__ bg,
                       const float* __restrict__ bq,
                       const float* __restrict__ Wq,
                       float* __restrict__ out) {
    __shared__ float wqs[A_ * S_];    // [a][s]
    __shared__ float key_s[A_ * M_];
    __shared__ float tok_s[M_ * 2];
    __shared__ float gate_s[M_];
    __shared__ float qs_s[A_];
    __shared__ float step_s[S_];

    const int o  = blockIdx.x;
    const int b  = blockIdx.y;
    const int bx = b * O_ + o;
    const int t  = threadIdx.x;

    for (int i = t; i < A_ * S_; i += 128)
        wqs[i] = Wq[(i >> 5) * (D_ + S_) + D_ + (i & 31)];

    if (t < M_) {
        const int m = t;
        const float ph = (m < 8) ? ts_out[bx * 2] : ts_out[bx * 2 + 1];
        const int   k  = (m < 8) ? (m + 1) : (m - 7);
        const float ang = 6.283185307179586477f * ph * (float)k;
        float sn, cs;
        sincosf(ang, &sn, &cs);
        tok_s[2 * m]     = sn;
        tok_s[2 * m + 1] = cs;
        const float g = tanhf(sn * Wg[0] + cs * Wg[1] + bg[0]);
        gate_s[m] = g;
        out[GATE_OFF + (size_t)bx * M_ + m] = g;
    }
    if (t >= 32 && t < 64) step_s[t - 32] = step_emb[bx * S_ + t - 32];
    __syncthreads();

    for (int i = t; i < A_ * M_; i += 128) {
        const int a = i / 12, m = i - a * 12;
        const float kv = tok_s[2 * m] * Wk[2 * a] + tok_s[2 * m + 1] * Wk[2 * a + 1]
                       + key_emb[m * A_ + a];
        key_s[i] = kv;
        g_key[(size_t)bx * (A_ * M_) + i] = kv;
    }
    for (int i = t; i < M_ * D_; i += 128)
        g_val[(size_t)bx * (M_ * D_) + i] = gate_s[i >> 6] * val_emb[i];
    if (t < A_) {
        float acc = bq[t];
        #pragma unroll
        for (int s = 0; s < S_; s++) acc += step_s[s] * wqs[t * S_ + s];
        qs_s[t] = acc;
    }
    __syncthreads();

    if (t < M_) {
        float acc = 0.f;
        #pragma unroll
        for (int a = 0; a < A_; a++) acc += qs_s[a] * key_s[a * 12 + t];
        g_c[(size_t)bx * M_ + t] = acc;
    }
}

// ============================================================================
// Kernel 2: main. Block = 64 n x 6 o (o-half), 256 threads.
// qh computed IN-BLOCK by warps 0-3 (2 threads/n, split-D) while warps 4-7
// stage key/val from global. Wq[:, :D] staged into at_sh (dead until phase A).
//   smem (floats): key 2304 | val 4608 | c 72 | at 4608 | qh 64*36=2304
// ============================================================================
#define SMEM_FLOATS 13896

__global__ __launch_bounds__(256, 4)
void attn_kernel(const float* __restrict__ H,
                 const float* __restrict__ Wq,
                 float* __restrict__ out) {
    extern __shared__ float sh[];
    float* key_sh = sh;             // [ol][a][m]  2304
    float* val_sh = sh + 2304;      // [ol][m][d]  4608
    float* c_sh   = sh + 6912;      // [ol][m] 72
    float* at_sh  = sh + 6984;      // phase<A: wq [a]*72+halfmap (2304); phase A+: at
    float* qh_sh  = sh + 11592;     // [nl][a] stride QSTRIDE

    const int t   = threadIdx.x;
    const int b   = blockIdx.z;
    const int oh  = blockIdx.y;
    const int n0  = blockIdx.x * 64;
    const int ob0 = b * O_ + oh * 6;

    // ---- step 1: stage Wq[:, :D] into at_sh; c into c_sh ----
    {
        float4* wq4 = (float4*)at_sh;
        const float4* Wq4 = (const float4*)Wq;
        for (int i = t; i < 512; i += 256) {
            const int a = i >> 4, j = i & 15;          // j: 16B chunk of d (0..15)
            // row a at a*18 f4; half0 chunks 0..7 at +0..7, half1 at +9..16
            wq4[a * 18 + j + ((j >= 8) ? 1 : 0)] = Wq4[a * 24 + j];
        }
        if (t < 72) c_sh[t] = g_c[(size_t)ob0 * M_ + t];
    }
    __syncthreads();

    // ---- step 2: warps 0-3 compute qh; warps 4-7 stage key/val ----
    if (t < 128) {
        const int nl   = t >> 1;
        const int half = t & 1;
        const float4* Hp = (const float4*)(H + ((size_t)b * NN + n0 + nl) * D_ + half * 32);
        ull hp[16];
        #pragma unroll
        for (int i = 0; i < 8; i++) {
            float4 v = Hp[i];
            hp[2 * i]     = pack2(v.x, v.y);
            hp[2 * i + 1] = pack2(v.z, v.w);
        }
        #pragma unroll
        for (int g = 0; g < 4; g++) {               // groups of 8 a (keeps regs low)
            float qv[8];
            #pragma unroll
            for (int aa = 0; aa < 8; aa++) {
                const int a = g * 8 + aa;
                const ulonglong2* wr = (const ulonglong2*)(at_sh + a * 72 + half * 36);
                ull acc = 0ull;
                #pragma unroll
                for (int j = 0; j < 8; j++) {       // pairs (2j, 2j+1) of this half
                    ulonglong2 w = wr[j];
                    acc = ffma2(hp[2 * j],     w.x, acc);
                    acc = ffma2(hp[2 * j + 1], w.y, acc);
                }
                float2 f = unpack2(acc);
                const float part = f.x + f.y;
                qv[aa] = part + __shfl_xor_sync(0xffffffffu, part, 1);
            }
            const float4 vout = half ? make_float4(qv[4], qv[5], qv[6], qv[7])
                                     : make_float4(qv[0], qv[1], qv[2], qv[3]);
            *(float4*)(qh_sh + nl * QSTRIDE + g * 8 + half * 4) = vout;
        }
    } else {
        const int tt = t - 128;
        const float4* gk = (const float4*)(g_key + (size_t)ob0 * (A_ * M_));
        float4* k4 = (float4*)key_sh;
        for (int i = tt; i < 576; i += 128) k4[i] = gk[i];
        const float4* gv = (const float4*)(g_val + (size_t)ob0 * (M_ * D_));
        float4* v4 = (float4*)val_sh;
        for (int i = tt; i < 1152; i += 128) v4[i] = gv[i];
    }
    __syncthreads();

    // ---- phase A: job = (nl, ol); logits, softmax -> at_sh (overwrites wq) ----
    for (int j = t; j < 384; j += 256) {
        const int nl = j & 63;
        const int ol = j >> 6;

        ull lg[6];
        const float* cp = c_sh + ol * M_;
        #pragma unroll
        for (int p = 0; p < 6; p++) lg[p] = pack2(cp[2 * p], cp[2 * p + 1]);

        float qh[A_];
        {
            const float4* qp4 = (const float4*)(qh_sh + nl * QSTRIDE);
            #pragma unroll
            for (int q = 0; q < 8; q++) {
                float4 v = qp4[q];
                qh[4*q] = v.x; qh[4*q+1] = v.y; qh[4*q+2] = v.z; qh[4*q+3] = v.w;
            }
        }
        const float* kp = key_sh + ol * (A_ * M_);
        #pragma unroll
        for (int a = 0; a < A_; a++) {
            const ull q2 = pack2(qh[a], qh[a]);
            const ulonglong2* kr = (const ulonglong2*)(kp + a * M_);
            ulonglong2 k0 = kr[0], k1 = kr[1], k2 = kr[2];
            lg[0] = ffma2(q2, k0.x, lg[0]);
            lg[1] = ffma2(q2, k0.y, lg[1]);
            lg[2] = ffma2(q2, k1.x, lg[2]);
            lg[3] = ffma2(q2, k1.y, lg[3]);
            lg[4] = ffma2(q2, k2.x, lg[4]);
            lg[5] = ffma2(q2, k2.y, lg[5]);
        }
        float l[M_];
        #pragma unroll
        for (int p = 0; p < 6; p++) {
            float2 f = unpack2(lg[p]);
            l[2 * p] = f.x; l[2 * p + 1] = f.y;
        }
        float mx = l[0];
        #pragma unroll
        for (int m = 1; m < M_; m++) mx = fmaxf(mx, l[m]);
        float ssum = 0.f, at[M_];
        #pragma unroll
        for (int m = 0; m < M_; m++) {
            const float e = __expf((l[m] - mx) * SCALE);
            at[m] = e; ssum += e;
        }
        const float inv = __frcp_rn(ssum);
        #pragma unroll
        for (int m = 0; m < M_; m++) at[m] *= inv;

        float4* as = (float4*)(at_sh + (ol * 64 + nl) * M_);
        as[0] = make_float4(at[0], at[1], at[2],  at[3]);
        as[1] = make_float4(at[4], at[5], at[6],  at[7]);
        as[2] = make_float4(at[8], at[9], at[10], at[11]);
    }
    __syncthreads();

    // ---- attn output: coalesced copy at_sh -> global ----
    if (t < 192) {
        #pragma unroll
        for (int ol = 0; ol < 6; ol++) {
            float4 v = *(const float4*)(at_sh + ol * 768 + t * 4);
            *(float4*)(out + ATT_OFF + ((size_t)(ob0 + ol) * NN + n0) * M_ + t * 4) = v;
        }
    }

    // ---- phase B: thread = (dq2 8B-chunk, nn0); val hoisted per o ----
    const int dq2 = t & 31;
    const int nn0 = t >> 5;
    const ull ALPHA2 = pack2(0.1f, 0.1f);

    ull hh[8];
    #pragma unroll
    for (int p = 0; p < 8; p++)
        hh[p] = *(const ull*)(H + ((size_t)b * NN + n0 + p * 8 + nn0) * D_ + dq2 * 2);

    #pragma unroll 1
    for (int ol = 0; ol < 6; ol++) {
        ull vv[M_];
        const float* vb = val_sh + ol * (M_ * D_) + dq2 * 2;
        #pragma unroll
        for (int m = 0; m < M_; m++) vv[m] = *(const ull*)(vb + m * D_);

        const float* atb = at_sh + ol * 64 * M_;
        float* ob = out + ((size_t)(ob0 + ol) * NN + n0) * D_ + dq2 * 2;
        #pragma unroll
        for (int p = 0; p < 8; p++) {
            const int nn = p * 8 + nn0;
            const float4* ap = (const float4*)(atb + nn * M_);
            float4 u0 = ap[0], u1 = ap[1], u2 = ap[2];
            ull acc = 0ull;
            acc = ffma2(pack2(u0.x, u0.x), vv[0],  acc);
            acc = ffma2(pack2(u0.y, u0.y), vv[1],  acc);
            acc = ffma2(pack2(u0.z, u0.z), vv[2],  acc);
            acc = ffma2(pack2(u0.w, u0.w), vv[3],  acc);
            acc = ffma2(pack2(u1.x, u1.x), vv[4],  acc);
            acc = ffma2(pack2(u1.y, u1.y), vv[5],  acc);
            acc = ffma2(pack2(u1.z, u1.z), vv[6],  acc);
            acc = ffma2(pack2(u1.w, u1.w), vv[7],  acc);
            acc = ffma2(pack2(u2.x, u2.x), vv[8],  acc);
            acc = ffma2(pack2(u2.y, u2.y), vv[9],  acc);
            acc = ffma2(pack2(u2.z, u2.z), vv[10], acc);
            acc = ffma2(pack2(u2.w, u2.w), vv[11], acc);
            *(ull*)(ob + (size_t)nn * D_) = ffma2(acc, ALPHA2, hh[p]);
        }
    }
}

// ============================================================================
extern "C" void kernel_launch(void* const* d_in, const int* in_sizes, int n_in,
                              void* d_out, int out_size) {
    const float* H        = (const float*)d_in[0];
    const float* ts_out   = (const float*)d_in[1];
    const float* step_emb = (const float*)d_in[2];
    const float* key_emb  = (const float*)d_in[3];
    const float* val_emb  = (const float*)d_in[4];
    const float* Wk       = (const float*)d_in[5];
    const float* Wg       = (const float*)d_in[6];
    const float* bg       = (const float*)d_in[7];
    const float* Wq       = (const float*)d_in[8];
    const float* bq       = (const float*)d_in[9];
    float* out = (float*)d_out;

    precompute_kernel<<<dim3(O_, B_), 128>>>(ts_out, step_emb, key_emb, val_emb,
                                             Wk, Wg, bg, bq, Wq, out);

    const int smem_bytes = SMEM_FLOATS * 4;  // 55584 B
    cudaFuncSetAttribute(attn_kernel, cudaFuncAttributeMaxDynamicSharedMemorySize,
                         smem_bytes);
    attn_kernel<<<dim3(NN / 64, 2, B_), 256, smem_bytes>>>(H, Wq, out);
}

// round 14
// speedup vs baseline: 1.0540x; 1.0540x over previous
#include <cuda_runtime.h>
#include <math.h>

// Problem constants
#define B_  16
#define NN  4096
#define D_  64
#define O_  12
#define S_  32
#define M_  12
#define A_  32

// Output layout: H_time [B,O,N,D] ++ attn [B,O,N,M] ++ gate [B,O,M]
#define ATT_OFF  50331648ull
#define GATE_OFF 59768832ull
#define SCALE 0.17677669529663688f   // 1/sqrt(32)

#define QSTRIDE 36   // qh row stride in floats: 9x16B -> LDS.128-aligned, conflict-free

// Scratch
__device__ float g_key[B_*O_*A_*M_];      // [b][o][a][m]
__device__ float g_val[B_*O_*M_*D_];      // [b][o][m][d]  (gate folded in)
__device__ float g_c  [B_*O_*M_];         // [b][o][m]     (qs . key)
__device__ float g_Q  [(size_t)B_*NN*A_]; // [b][n][a]

typedef unsigned long long ull;

__device__ __forceinline__ ull ffma2(ull a, ull b, ull c) {
    ull d;
    asm("fma.rn.f32x2 %0, %1, %2, %3;" : "=l"(d) : "l"(a), "l"(b), "l"(c));
    return d;
}
__device__ __forceinline__ ull pack2(float x, float y) {
    ull r;
    asm("mov.b64 %0, {%1, %2};" : "=l"(r) : "r"(__float_as_uint(x)), "r"(__float_as_uint(y)));
    return r;
}
__device__ __forceinline__ float2 unpack2(ull v) {
    unsigned int lo, hi;
    asm("mov.b64 {%0, %1}, %2;" : "=r"(lo), "=r"(hi) : "l"(v));
    return make_float2(__uint_as_float(lo), __uint_as_float(hi));
}

// ============================================================================
// Kernel 1 (fused prep):
//   bx <  64 : qh for 64-n tile (2 threads/n, split-D, ALL global access coalesced)
//   bx >= 64 : precompute for single o = bx - 64
// Dynamic smem: 9216 floats (36864 B)
// ============================================================================
__global__ __launch_bounds__(128)
void prep_kernel(const float* __restrict__ H,
                 const float* __restrict__ ts_out,
                 const float* __restrict__ step_emb,
                 const float* __restrict__ key_emb,
                 const float* __restrict__ val_emb,
                 const float* __restrict__ Wk,
                 const float* __restrict__ Wg,
                 const float* __restrict__ bg,
                 const float* __restrict__ bq,
                 const float* __restrict__ Wq,
                 float* __restrict__ out) {
    extern __shared__ float ps[];
    const int b = blockIdx.y;
    const int t = threadIdx.x;

    if (blockIdx.x < 64) {
        // ---------------- qh: 64 n, 2 threads/n ----------------
        float* wq_sh = ps;            // [a] stride 72: half0 at +0, half1 at +36
        float* h_sh  = ps + 2304;     // [nl] stride 72: half0 at +0, half1 at +36
        float* q_sh  = ps + 6912;     // [nl] stride 36

        const int n0 = blockIdx.x * 64;

        // stage Wq[:, :D] (coalesced LDG)
        for (int i = t; i < 2048; i += 128) {
            const int a = i >> 6, d = i & 63;
            wq_sh[a * 72 + ((d >= 32) ? (d + 4) : d)] = Wq[a * (D_ + S_) + d];
        }
        // stage H tile (fully coalesced: warp = 512B contiguous)
        {
            const float4* Hg = (const float4*)(H + ((size_t)b * NN + n0) * D_);
            for (int i = t; i < 1024; i += 128) {
                float4 v = Hg[i];
                const int row = i >> 4, j = i & 15;
                *(float4*)(h_sh + row * 72 + j * 4 + ((j >= 8) ? 4 : 0)) = v;
            }
        }
        __syncthreads();

        const int nl   = t >> 1;
        const int half = t & 1;

        // H half-row from smem (conflict-free: banks (l>>1)*8+(l&1)*4+4j distinct)
        ull hp[16];
        {
            const float4* hr = (const float4*)(h_sh + nl * 72 + half * 36);
            #pragma unroll
            for (int i = 0; i < 8; i++) {
                float4 v = hr[i];
                hp[2 * i]     = pack2(v.x, v.y);
                hp[2 * i + 1] = pack2(v.z, v.w);
            }
        }

        #pragma unroll
        for (int g = 0; g < 4; g++) {             // 8 a's per group (regs low)
            float qv[8];
            #pragma unroll
            for (int aa = 0; aa < 8; aa++) {
                const int a = g * 8 + aa;
                const ulonglong2* wr = (const ulonglong2*)(wq_sh + a * 72 + half * 36);
                ull acc = 0ull;
                #pragma unroll
                for (int j = 0; j < 8; j++) {     // pairs (2j, 2j+1) of this half
                    ulonglong2 w = wr[j];
                    acc = ffma2(hp[2 * j],     w.x, acc);
                    acc = ffma2(hp[2 * j + 1], w.y, acc);
                }
                float2 f = unpack2(acc);
                const float part = f.x + f.y;
                qv[aa] = part + __shfl_xor_sync(0xffffffffu, part, 1);
            }
            const float4 vout = half ? make_float4(qv[4], qv[5], qv[6], qv[7])
                                     : make_float4(qv[0], qv[1], qv[2], qv[3]);
            *(float4*)(q_sh + nl * QSTRIDE + g * 8 + half * 4) = vout;
        }
        __syncthreads();

        // copy out q (coalesced STG: linear float4)
        {
            float4* Qo = (float4*)(g_Q + ((size_t)b * NN + n0) * A_);
            for (int i = t; i < 512; i += 128)
                Qo[i] = *(const float4*)(q_sh + (i >> 3) * QSTRIDE + (i & 7) * 4);
        }
    } else {
        // ---------------- precompute: ONE (b, o) per block ----------------
        float* wqs    = ps;           // [a][s] 1024
        float* key_s  = ps + 1024;    // 384
        float* tok_s  = ps + 1408;    // 24
        float* gate_s = ps + 1432;    // 12
        float* qs_s   = ps + 1444;    // 32
        float* step_s = ps + 1476;    // 32

        const int o  = blockIdx.x - 64;
        const int bx = b * O_ + o;

        for (int i = t; i < A_ * S_; i += 128)
            wqs[i] = Wq[(i >> 5) * (D_ + S_) + D_ + (i & 31)];

        if (t < M_) {
            const int m = t;
            const float ph = (m < 8) ? ts_out[bx * 2] : ts_out[bx * 2 + 1];
            const int   k  = (m < 8) ? (m + 1) : (m - 7);
            const float ang = 6.283185307179586477f * ph * (float)k;
            float sn, cs;
            sincosf(ang, &sn, &cs);
            tok_s[2 * m]     = sn;
            tok_s[2 * m + 1] = cs;
            const float g = tanhf(sn * Wg[0] + cs * Wg[1] + bg[0]);
            gate_s[m] = g;
            out[GATE_OFF + (size_t)bx * M_ + m] = g;
        }
        if (t >= 32 && t < 64) step_s[t - 32] = step_emb[bx * S_ + t - 32];
        __syncthreads();

        for (int i = t; i < A_ * M_; i += 128) {
            const int a = i / 12, m = i - a * 12;
            const float kv = tok_s[2 * m] * Wk[2 * a] + tok_s[2 * m + 1] * Wk[2 * a + 1]
                           + key_emb[m * A_ + a];
            key_s[i] = kv;
            g_key[(size_t)bx * (A_ * M_) + i] = kv;
        }
        for (int i = t; i < M_ * D_; i += 128)
            g_val[(size_t)bx * (M_ * D_) + i] = gate_s[i >> 6] * val_emb[i];
        if (t < A_) {
            float acc = bq[t];
            #pragma unroll
            for (int s = 0; s < S_; s++) acc += step_s[s] * wqs[t * S_ + s];
            qs_s[t] = acc;
        }
        __syncthreads();

        if (t < M_) {
            float acc = 0.f;
            #pragma unroll
            for (int a = 0; a < A_; a++) acc += qs_s[a] * key_s[a * 12 + t];
            g_c[(size_t)bx * M_ + t] = acc;
        }
    }
}

// ============================================================================
// Kernel 2: main (R12, unchanged). Block = 64 n x 6 o (o-half), 256 threads.
//   smem (floats): key 2304 | val 4608 | c 72 | at 4608 | qh 64*36=2304
// ============================================================================
#define SMEM_FLOATS 13896

__global__ __launch_bounds__(256, 4)
void attn_kernel(const float* __restrict__ H, float* __restrict__ out) {
    extern __shared__ float sh[];
    float* key_sh = sh;             // [ol][a][m]  2304
    float* val_sh = sh + 2304;      // [ol][m][d]  4608
    float* c_sh   = sh + 6912;      // [ol][m] 72
    float* at_sh  = sh + 6984;      // [ol*64+nl][m] 4608
    float* qh_sh  = sh + 11592;     // [nl][a] stride QSTRIDE

    const int t   = threadIdx.x;
    const int b   = blockIdx.z;
    const int oh  = blockIdx.y;
    const int n0  = blockIdx.x * 64;
    const int ob0 = b * O_ + oh * 6;

    // ---- stage tables (coalesced) ----
    {
        const float4* gk = (const float4*)(g_key + (size_t)ob0 * (A_ * M_));
        float4* k4 = (float4*)key_sh;
        for (int i = t; i < 576; i += 256) k4[i] = gk[i];
        const float4* gv = (const float4*)(g_val + (size_t)ob0 * (M_ * D_));
        float4* v4 = (float4*)val_sh;
        for (int i = t; i < 1152; i += 256) v4[i] = gv[i];
        if (t < 72) c_sh[t] = g_c[(size_t)ob0 * M_ + t];
        const float4* Qb = (const float4*)(g_Q + ((size_t)b * NN + n0) * A_);
        for (int i = t; i < 512; i += 256) {
            float4 v = Qb[i];
            *(float4*)(qh_sh + (i >> 3) * QSTRIDE + (i & 7) * 4) = v;
        }
    }
    __syncthreads();

    // ---- phase A: job = (nl, ol); logits, softmax -> at_sh ----
    for (int j = t; j < 384; j += 256) {
        const int nl = j & 63;
        const int ol = j >> 6;

        ull lg[6];
        const float* cp = c_sh + ol * M_;
        #pragma unroll
        for (int p = 0; p < 6; p++) lg[p] = pack2(cp[2 * p], cp[2 * p + 1]);

        float qh[A_];
        {
            const float4* qp4 = (const float4*)(qh_sh + nl * QSTRIDE);
            #pragma unroll
            for (int q = 0; q < 8; q++) {
                float4 v = qp4[q];
                qh[4*q] = v.x; qh[4*q+1] = v.y; qh[4*q+2] = v.z; qh[4*q+3] = v.w;
            }
        }
        const float* kp = key_sh + ol * (A_ * M_);
        #pragma unroll
        for (int a = 0; a < A_; a++) {
            const ull q2 = pack2(qh[a], qh[a]);
            const ulonglong2* kr = (const ulonglong2*)(kp + a * M_);
            ulonglong2 k0 = kr[0], k1 = kr[1], k2 = kr[2];
            lg[0] = ffma2(q2, k0.x, lg[0]);
            lg[1] = ffma2(q2, k0.y, lg[1]);
            lg[2] = ffma2(q2, k1.x, lg[2]);
            lg[3] = ffma2(q2, k1.y, lg[3]);
            lg[4] = ffma2(q2, k2.x, lg[4]);
            lg[5] = ffma2(q2, k2.y, lg[5]);
        }
        float l[M_];
        #pragma unroll
        for (int p = 0; p < 6; p++) {
            float2 f = unpack2(lg[p]);
            l[2 * p] = f.x; l[2 * p + 1] = f.y;
        }
        float mx = l[0];
        #pragma unroll
        for (int m = 1; m < M_; m++) mx = fmaxf(mx, l[m]);
        float ssum = 0.f, at[M_];
        #pragma unroll
        for (int m = 0; m < M_; m++) {
            const float e = __expf((l[m] - mx) * SCALE);
            at[m] = e; ssum += e;
        }
        const float inv = __frcp_rn(ssum);
        #pragma unroll
        for (int m = 0; m < M_; m++) at[m] *= inv;

        float4* as = (float4*)(at_sh + (ol * 64 + nl) * M_);
        as[0] = make_float4(at[0], at[1], at[2],  at[3]);
        as[1] = make_float4(at[4], at[5], at[6],  at[7]);
        as[2] = make_float4(at[8], at[9], at[10], at[11]);
    }
    __syncthreads();

    // ---- attn output: coalesced copy at_sh -> global ----
    if (t < 192) {
        #pragma unroll
        for (int ol = 0; ol < 6; ol++) {
            float4 v = *(const float4*)(at_sh + ol * 768 + t * 4);
            *(float4*)(out + ATT_OFF + ((size_t)(ob0 + ol) * NN + n0) * M_ + t * 4) = v;
        }
    }

    // ---- phase B: thread = (dq2 8B-chunk, nn0); val hoisted per o ----
    const int dq2 = t & 31;
    const int nn0 = t >> 5;
    const ull ALPHA2 = pack2(0.1f, 0.1f);

    ull hh[8];
    #pragma unroll
    for (int p = 0; p < 8; p++)
        hh[p] = *(const ull*)(H + ((size_t)b * NN + n0 + p * 8 + nn0) * D_ + dq2 * 2);

    #pragma unroll 1
    for (int ol = 0; ol < 6; ol++) {
        ull vv[M_];
        const float* vb = val_sh + ol * (M_ * D_) + dq2 * 2;
        #pragma unroll
        for (int m = 0; m < M_; m++) vv[m] = *(const ull*)(vb + m * D_);

        const float* atb = at_sh + ol * 64 * M_;
        float* ob = out + ((size_t)(ob0 + ol) * NN + n0) * D_ + dq2 * 2;
        #pragma unroll
        for (int p = 0; p < 8; p++) {
            const int nn = p * 8 + nn0;
            const float4* ap = (const float4*)(atb + nn * M_);
            float4 u0 = ap[0], u1 = ap[1], u2 = ap[2];
            ull acc = 0ull;
            acc = ffma2(pack2(u0.x, u0.x), vv[0],  acc);
            acc = ffma2(pack2(u0.y, u0.y), vv[1],  acc);
            acc = ffma2(pack2(u0.z, u0.z), vv[2],  acc);
            acc = ffma2(pack2(u0.w, u0.w), vv[3],  acc);
            acc = ffma2(pack2(u1.x, u1.x), vv[4],  acc);
            acc = ffma2(pack2(u1.y, u1.y), vv[5],  acc);
            acc = ffma2(pack2(u1.z, u1.z), vv[6],  acc);
            acc = ffma2(pack2(u1.w, u1.w), vv[7],  acc);
            acc = ffma2(pack2(u2.x, u2.x), vv[8],  acc);
            acc = ffma2(pack2(u2.y, u2.y), vv[9],  acc);
            acc = ffma2(pack2(u2.z, u2.z), vv[10], acc);
            acc = ffma2(pack2(u2.w, u2.w), vv[11], acc);
            *(ull*)(ob + (size_t)nn * D_) = ffma2(acc, ALPHA2, hh[p]);
        }
    }
}

// ============================================================================
extern "C" void kernel_launch(void* const* d_in, const int* in_sizes, int n_in,
                              void* d_out, int out_size) {
    const float* H        = (const float*)d_in[0];
    const float* ts_out   = (const float*)d_in[1];
    const float* step_emb = (const float*)d_in[2];
    const float* key_emb  = (const float*)d_in[3];
    const float* val_emb  = (const float*)d_in[4];
    const float* Wk       = (const float*)d_in[5];
    const float* Wg       = (const float*)d_in[6];
    const float* bg       = (const float*)d_in[7];
    const float* Wq       = (const float*)d_in[8];
    const float* bq       = (const float*)d_in[9];
    float* out = (float*)d_out;

    cudaFuncSetAttribute(prep_kernel, cudaFuncAttributeMaxDynamicSharedMemorySize,
                         9216 * 4);
    prep_kernel<<<dim3(64 + O_, B_), 128, 9216 * 4>>>(
        H, ts_out, step_emb, key_emb, val_emb, Wk, Wg, bg, bq, Wq, out);

    const int smem_bytes = SMEM_FLOATS * 4;  // 55584 B
    cudaFuncSetAttribute(attn_kernel, cudaFuncAttributeMaxDynamicSharedMemorySize,
                         smem_bytes);
    attn_kernel<<<dim3(NN / 64, 2, B_), 256, smem_bytes>>>(H, out);
}

// round 15
// speedup vs baseline: 1.0598x; 1.0055x over previous
#include <cuda_runtime.h>
#include <math.h>

// Problem constants
#define B_  16
#define NN  4096
#define D_  64
#define O_  12
#define S_  32
#define M_  12
#define A_  32

// Output layout: H_time [B,O,N,D] ++ attn [B,O,N,M] ++ gate [B,O,M]
#define ATT_OFF  50331648ull
#define GATE_OFF 59768832ull
#define SCALE 0.17677669529663688f   // 1/sqrt(32), folded into key/c at precompute

#define QSTRIDE 36   // qh row stride in floats: 9x16B -> LDS.128-aligned, conflict-free

// Scratch (key/c pre-scaled by SCALE)
__device__ float g_key[B_*O_*A_*M_];      // [b][o][a][m]
__device__ float g_val[B_*O_*M_*D_];      // [b][o][m][d]  (gate folded in)
__device__ float g_c  [B_*O_*M_];         // [b][o][m]

typedef unsigned long long ull;

__device__ __forceinline__ ull ffma2(ull a, ull b, ull c) {
    ull d;
    asm("fma.rn.f32x2 %0, %1, %2, %3;" : "=l"(d) : "l"(a), "l"(b), "l"(c));
    return d;
}
__device__ __forceinline__ ull pack2(float x, float y) {
    ull r;
    asm("mov.b64 %0, {%1, %2};" : "=l"(r) : "r"(__float_as_uint(x)), "r"(__float_as_uint(y)));
    return r;
}
__device__ __forceinline__ float2 unpack2(ull v) {
    unsigned int lo, hi;
    asm("mov.b64 {%0, %1}, %2;" : "=r"(lo), "=r"(hi) : "l"(v));
    return make_float2(__uint_as_float(lo), __uint_as_float(hi));
}

// ============================================================================
// Kernel 1: precompute for one (b, o) per block (key/c scaled by SCALE)
// ============================================================================
__global__ __launch_bounds__(128)
void precompute_kernel(const float* __restrict__ ts_out,
                       const float* __restrict__ step_emb,
                       const float* __restrict__ key_emb,
                       const float* __restrict__ val_emb,
                       const float* __restrict__ Wk,
                       const float* __restrict__ Wg,
                       const float* __restrict__ bg,
                       const float* __restrict__ bq,
                       const float* __restrict__ Wq,
                       float* __restrict__ out) {
    __shared__ float wqs[A_ * S_];    // [a][s]
    __shared__ float key_s[A_ * M_];  // scaled
    __shared__ float tok_s[M_ * 2];
    __shared__ float gate_s[M_];
    __shared__ float qs_s[A_];
    __shared__ float step_s[S_];

    const int o  = blockIdx.x;
    const int b  = blockIdx.y;
    const int bx = b * O_ + o;
    const int t  = threadIdx.x;

    for (int i = t; i < A_ * S_; i += 128)
        wqs[i] = Wq[(i >> 5) * (D_ + S_) + D_ + (i & 31)];

    if (t < M_) {
        const int m = t;
        const float ph = (m < 8) ? ts_out[bx * 2] : ts_out[bx * 2 + 1];
        const int   k  = (m < 8) ? (m + 1) : (m - 7);
        const float ang = 6.283185307179586477f * ph * (float)k;
        float sn, cs;
        sincosf(ang, &sn, &cs);
        tok_s[2 * m]     = sn;
        tok_s[2 * m + 1] = cs;
        const float g = tanhf(sn * Wg[0] + cs * Wg[1] + bg[0]);
        gate_s[m] = g;
        out[GATE_OFF + (size_t)bx * M_ + m] = g;
    }
    if (t >= 32 && t < 64) step_s[t - 32] = step_emb[bx * S_ + t - 32];
    __syncthreads();

    for (int i = t; i < A_ * M_; i += 128) {
        const int a = i / 12, m = i - a * 12;
        const float kv = (tok_s[2 * m] * Wk[2 * a] + tok_s[2 * m + 1] * Wk[2 * a + 1]
                          + key_emb[m * A_ + a]) * SCALE;
        key_s[i] = kv;
        g_key[(size_t)bx * (A_ * M_) + i] = kv;
    }
    for (int i = t; i < M_ * D_; i += 128)
        g_val[(size_t)bx * (M_ * D_) + i] = gate_s[i >> 6] * val_emb[i];
    if (t < A_) {
        float acc = bq[t];
        #pragma unroll
        for (int s = 0; s < S_; s++) acc += step_s[s] * wqs[t * S_ + s];
        qs_s[t] = acc;
    }
    __syncthreads();

    if (t < M_) {
        float acc = 0.f;
        #pragma unroll
        for (int a = 0; a < A_; a++) acc += qs_s[a] * key_s[a * 12 + t];
        g_c[(size_t)bx * M_ + t] = acc;   // already scaled via key_s
    }
}

// ============================================================================
// Kernel 2: single main kernel. Block = 64 n x ALL 12 o, 512 threads, 2/SM.
// qh computed in-block (4 threads/n, warps 0-7) while warps 8-15 stage key/val.
//   smem (floats): key 4608 | val 9216 | c 144 | at 9216 | qh 64*36=2304
//   at_sh doubles as Wq[:, :D] scratch (stride-80 rows, quarter offset 20).
// ============================================================================
#define SMEM_FLOATS 25488

__global__ __launch_bounds__(512, 2)
void attn_kernel(const float* __restrict__ H,
                 const float* __restrict__ Wq,
                 float* __restrict__ out) {
    extern __shared__ float sh[];
    float* key_sh = sh;               // [o][a][m]   4608
    float* val_sh = sh + 4608;        // [o][m][d]   9216
    float* c_sh   = sh + 13824;       // [o][m]      144
    float* at_sh  = sh + 13968;       // [o*64+nl][m] 9216 (scratch: wq stride-80)
    float* qh_sh  = sh + 23184;       // [nl][a] stride QSTRIDE

    const int t   = threadIdx.x;
    const int b   = blockIdx.y;
    const int n0  = blockIdx.x * 64;
    const int ob0 = b * O_;

    // ---- step 1: stage Wq[:, :D] into at_sh scratch; c into c_sh ----
    {
        // row a: 20 float4 (quarter q at f4 offset a*20 + q*5)
        const int a = t >> 4, j = t & 15;
        ((float4*)at_sh)[a * 20 + (j >> 2) * 5 + (j & 3)] =
            ((const float4*)Wq)[a * 24 + j];
        if (t < 144) c_sh[t] = g_c[(size_t)b * 144 + t];
    }
    __syncthreads();

    // ---- step 2: warps 0-7 compute qh (4 thr/n); warps 8-15 stage key/val ----
    if (t < 256) {
        const int nl = t >> 2;
        const int q  = t & 3;
        // H quarter (16 floats): nL=16 per LDG, 4 LDGs reuse lines
        const float4* Hq = (const float4*)(H + ((size_t)b * NN + n0 + nl) * D_ + q * 16);
        ull hp[8];
        #pragma unroll
        for (int i = 0; i < 4; i++) {
            float4 v = Hq[i];
            hp[2 * i]     = pack2(v.x, v.y);
            hp[2 * i + 1] = pack2(v.z, v.w);
        }
        #pragma unroll
        for (int g = 0; g < 4; g++) {
            float qv[8];
            #pragma unroll
            for (int aa = 0; aa < 8; aa++) {
                const int a = g * 8 + aa;
                const ulonglong2* wr =
                    (const ulonglong2*)(at_sh + a * 80 + q * 20);
                ull acc = 0ull;
                #pragma unroll
                for (int j2 = 0; j2 < 4; j2++) {
                    ulonglong2 w = wr[j2];
                    acc = ffma2(hp[2 * j2],     w.x, acc);
                    acc = ffma2(hp[2 * j2 + 1], w.y, acc);
                }
                float2 f = unpack2(acc);
                float part = f.x + f.y;
                part += __shfl_xor_sync(0xffffffffu, part, 1);
                part += __shfl_xor_sync(0xffffffffu, part, 2);
                qv[aa] = part;
            }
            if (q == g) {   // thread q stores a-group g (8 floats = 2 STS.128)
                *(float4*)(qh_sh + nl * QSTRIDE + g * 8) =
                    make_float4(qv[0], qv[1], qv[2], qv[3]);
                *(float4*)(qh_sh + nl * QSTRIDE + g * 8 + 4) =
                    make_float4(qv[4], qv[5], qv[6], qv[7]);
            }
        }
    } else {
        const int tt = t - 256;
        const float4* gk = (const float4*)(g_key + (size_t)ob0 * (A_ * M_));
        float4* k4 = (float4*)key_sh;
        for (int i = tt; i < 1152; i += 256) k4[i] = gk[i];
        const float4* gv = (const float4*)(g_val + (size_t)ob0 * (M_ * D_));
        float4* v4 = (float4*)val_sh;
        for (int i = tt; i < 2304; i += 256) v4[i] = gv[i];
    }
    __syncthreads();

    // ---- phase A: job = (nl, ol); logits, softmax -> at_sh (overwrites wq) ----
    for (int j = t; j < 768; j += 512) {
        const int nl = j & 63;
        const int ol = j >> 6;

        ull lg[6];
        const float* cp = c_sh + ol * M_;
        #pragma unroll
        for (int p = 0; p < 6; p++) lg[p] = pack2(cp[2 * p], cp[2 * p + 1]);

        float qh[A_];
        {
            const float4* qp4 = (const float4*)(qh_sh + nl * QSTRIDE);
            #pragma unroll
            for (int q = 0; q < 8; q++) {
                float4 v = qp4[q];
                qh[4*q] = v.x; qh[4*q+1] = v.y; qh[4*q+2] = v.z; qh[4*q+3] = v.w;
            }
        }
        const float* kp = key_sh + ol * (A_ * M_);
        #pragma unroll
        for (int a = 0; a < A_; a++) {
            const ull q2 = pack2(qh[a], qh[a]);
            const ulonglong2* kr = (const ulonglong2*)(kp + a * M_);
            ulonglong2 k0 = kr[0], k1 = kr[1], k2 = kr[2];
            lg[0] = ffma2(q2, k0.x, lg[0]);
            lg[1] = ffma2(q2, k0.y, lg[1]);
            lg[2] = ffma2(q2, k1.x, lg[2]);
            lg[3] = ffma2(q2, k1.y, lg[3]);
            lg[4] = ffma2(q2, k2.x, lg[4]);
            lg[5] = ffma2(q2, k2.y, lg[5]);
        }
        float l[M_];
        #pragma unroll
        for (int p = 0; p < 6; p++) {
            float2 f = unpack2(lg[p]);
            l[2 * p] = f.x; l[2 * p + 1] = f.y;
        }
        float mx = l[0];
        #pragma unroll
        for (int m = 1; m < M_; m++) mx = fmaxf(mx, l[m]);
        float ssum = 0.f, at[M_];
        #pragma unroll
        for (int m = 0; m < M_; m++) {
            const float e = __expf(l[m] - mx);   // SCALE pre-folded
            at[m] = e; ssum += e;
        }
        const float inv = __frcp_rn(ssum);
        #pragma unroll
        for (int m = 0; m < M_; m++) at[m] *= inv;

        float4* as = (float4*)(at_sh + (ol * 64 + nl) * M_);
        as[0] = make_float4(at[0], at[1], at[2],  at[3]);
        as[1] = make_float4(at[4], at[5], at[6],  at[7]);
        as[2] = make_float4(at[8], at[9], at[10], at[11]);
    }
    __syncthreads();

    // ---- attn output: coalesced copy at_sh -> global (2304 f4 over 512 thr) ----
    for (int i = t; i < 2304; i += 512) {
        const int ol = i / 192, r = i - ol * 192;
        float4 v = ((const float4*)at_sh)[i];
        *(float4*)(out + ATT_OFF + ((size_t)(ob0 + ol) * NN + n0) * M_ + r * 4) = v;
    }

    // ---- phase B: thread = (dq2 8B-chunk, nn0 0..15); val hoisted per o ----
    const int dq2 = t & 31;
    const int nn0 = t >> 5;          // 0..15 (one per warp)
    const ull ALPHA2 = pack2(0.1f, 0.1f);

    ull hh[4];
    #pragma unroll
    for (int p = 0; p < 4; p++)
        hh[p] = *(const ull*)(H + ((size_t)b * NN + n0 + p * 16 + nn0) * D_ + dq2 * 2);

    #pragma unroll 1
    for (int ol = 0; ol < O_; ol++) {
        ull vv[M_];
        const float* vb = val_sh + ol * (M_ * D_) + dq2 * 2;
        #pragma unroll
        for (int m = 0; m < M_; m++) vv[m] = *(const ull*)(vb + m * D_);

        const float* atb = at_sh + ol * 64 * M_;
        float* ob = out + ((size_t)(ob0 + ol) * NN + n0) * D_ + dq2 * 2;
        #pragma unroll
        for (int p = 0; p < 4; p++) {
            const int nn = p * 16 + nn0;
            const float4* ap = (const float4*)(atb + nn * M_);
            float4 u0 = ap[0], u1 = ap[1], u2 = ap[2];
            ull acc = 0ull;
            acc = ffma2(pack2(u0.x, u0.x), vv[0],  acc);
            acc = ffma2(pack2(u0.y, u0.y), vv[1],  acc);
            acc = ffma2(pack2(u0.z, u0.z), vv[2],  acc);
            acc = ffma2(pack2(u0.w, u0.w), vv[3],  acc);
            acc = ffma2(pack2(u1.x, u1.x), vv[4],  acc);
            acc = ffma2(pack2(u1.y, u1.y), vv[5],  acc);
            acc = ffma2(pack2(u1.z, u1.z), vv[6],  acc);
            acc = ffma2(pack2(u1.w, u1.w), vv[7],  acc);
            acc = ffma2(pack2(u2.x, u2.x), vv[8],  acc);
            acc = ffma2(pack2(u2.y, u2.y), vv[9],  acc);
            acc = ffma2(pack2(u2.z, u2.z), vv[10], acc);
            acc = ffma2(pack2(u2.w, u2.w), vv[11], acc);
            *(ull*)(ob + (size_t)nn * D_) = ffma2(acc, ALPHA2, hh[p]);
        }
    }
}

// ============================================================================
extern "C" void kernel_launch(void* const* d_in, const int* in_sizes, int n_in,
                              void* d_out, int out_size) {
    const float* H        = (const float*)d_in[0];
    const float* ts_out   = (const float*)d_in[1];
    const float* step_emb = (const float*)d_in[2];
    const float* key_emb  = (const float*)d_in[3];
    const float* val_emb  = (const float*)d_in[4];
    const float* Wk       = (const float*)d_in[5];
    const float* Wg       = (const float*)d_in[6];
    const float* bg       = (const float*)d_in[7];
    const float* Wq       = (const float*)d_in[8];
    const float* bq       = (const float*)d_in[9];
    float* out = (float*)d_out;

    precompute_kernel<<<dim3(O_, B_), 128>>>(ts_out, step_emb, key_emb, val_emb,
                                             Wk, Wg, bg, bq, Wq, out);

    const int smem_bytes = SMEM_FLOATS * 4;  // 101952 B
    cudaFuncSetAttribute(attn_kernel, cudaFuncAttributeMaxDynamicSharedMemorySize,
                         smem_bytes);
    attn_kernel<<<dim3(NN / 64, B_), 512, smem_bytes>>>(H, Wq, out);
}

// round 16
// speedup vs baseline: 1.1224x; 1.0591x over previous
#include <cuda_runtime.h>
#include <math.h>

// Problem constants
#define B_  16
#define NN  4096
#define D_  64
#define O_  12
#define S_  32
#define M_  12
#define A_  32

// Output layout: H_time [B,O,N,D] ++ attn [B,O,N,M] ++ gate [B,O,M]
#define ATT_OFF  50331648ull
#define GATE_OFF 59768832ull
#define SCALE 0.17677669529663688f   // 1/sqrt(32), folded into key/c at precompute

#define QSTRIDE 36   // qh row stride in floats: 9x16B -> LDS.128-aligned, conflict-free

// Scratch (key/c pre-scaled by SCALE)
__device__ float g_key[B_*O_*A_*M_];      // [b][o][a][m]
__device__ float g_val[B_*O_*M_*D_];      // [b][o][m][d]  (gate folded in)
__device__ float g_c  [B_*O_*M_];         // [b][o][m]

typedef unsigned long long ull;

__device__ __forceinline__ ull ffma2(ull a, ull b, ull c) {
    ull d;
    asm("fma.rn.f32x2 %0, %1, %2, %3;" : "=l"(d) : "l"(a), "l"(b), "l"(c));
    return d;
}
__device__ __forceinline__ ull pack2(float x, float y) {
    ull r;
    asm("mov.b64 %0, {%1, %2};" : "=l"(r) : "r"(__float_as_uint(x)), "r"(__float_as_uint(y)));
    return r;
}
__device__ __forceinline__ float2 unpack2(ull v) {
    unsigned int lo, hi;
    asm("mov.b64 {%0, %1}, %2;" : "=r"(lo), "=r"(hi) : "l"(v));
    return make_float2(__uint_as_float(lo), __uint_as_float(hi));
}

// ============================================================================
// Kernel 1: precompute for one (b, o) per block (key/c scaled by SCALE)
// ============================================================================
__global__ __launch_bounds__(128)
void precompute_kernel(const float* __restrict__ ts_out,
                       const float* __restrict__ step_emb,
                       const float* __restrict__ key_emb,
                       const float* __restrict__ val_emb,
                       const float* __restrict__ Wk,
                       const float* __restrict__ Wg,
                       const float* __restrict__ bg,
                       const float* __restrict__ bq,
                       const float* __restrict__ Wq,
                       float* __restrict__ out) {
    __shared__ float wqs[A_ * S_];    // [a][s]
    __shared__ float key_s[A_ * M_];  // scaled
    __shared__ float tok_s[M_ * 2];
    __shared__ float gate_s[M_];
    __shared__ float qs_s[A_];
    __shared__ float step_s[S_];

    const int o  = blockIdx.x;
    const int b  = blockIdx.y;
    const int bx = b * O_ + o;
    const int t  = threadIdx.x;

    for (int i = t; i < A_ * S_; i += 128)
        wqs[i] = Wq[(i >> 5) * (D_ + S_) + D_ + (i & 31)];

    if (t < M_) {
        const int m = t;
        const float ph = (m < 8) ? ts_out[bx * 2] : ts_out[bx * 2 + 1];
        const int   k  = (m < 8) ? (m + 1) : (m - 7);
        const float ang = 6.283185307179586477f * ph * (float)k;
        float sn, cs;
        sincosf(ang, &sn, &cs);
        tok_s[2 * m]     = sn;
        tok_s[2 * m + 1] = cs;
        const float g = tanhf(sn * Wg[0] + cs * Wg[1] + bg[0]);
        gate_s[m] = g;
        out[GATE_OFF + (size_t)bx * M_ + m] = g;
    }
    if (t >= 32 && t < 64) step_s[t - 32] = step_emb[bx * S_ + t - 32];
    __syncthreads();

    for (int i = t; i < A_ * M_; i += 128) {
        const int a = i / 12, m = i - a * 12;
        const float kv = (tok_s[2 * m] * Wk[2 * a] + tok_s[2 * m + 1] * Wk[2 * a + 1]
                          + key_emb[m * A_ + a]) * SCALE;
        key_s[i] = kv;
        g_key[(size_t)bx * (A_ * M_) + i] = kv;
    }
    for (int i = t; i < M_ * D_; i += 128)
        g_val[(size_t)bx * (M_ * D_) + i] = gate_s[i >> 6] * val_emb[i];
    if (t < A_) {
        float acc = bq[t];
        #pragma unroll
        for (int s = 0; s < S_; s++) acc += step_s[s] * wqs[t * S_ + s];
        qs_s[t] = acc;
    }
    __syncthreads();

    if (t < M_) {
        float acc = 0.f;
        #pragma unroll
        for (int a = 0; a < A_; a++) acc += qs_s[a] * key_s[a * 12 + t];
        g_c[(size_t)bx * M_ + t] = acc;   // already scaled via key_s
    }
}

// ============================================================================
// Kernel 2: single main kernel. Block = 64 n x ALL 12 o, 512 threads, 2/SM.
// qh computed in-block (4 threads/n, warps 0-7) while warps 8-15 stage key/val.
// Phase A: 2 n per thread, f32x2 lanes = (n1, n2) -> key LDS halved.
//   smem (floats): key 4608 | val 9216 | c 144 | at 9216 | qh 64*36=2304
// ============================================================================
#define SMEM_FLOATS 25488

__global__ __launch_bounds__(512, 2)
void attn_kernel(const float* __restrict__ H,
                 const float* __restrict__ Wq,
                 float* __restrict__ out) {
    extern __shared__ float sh[];
    float* key_sh = sh;               // [o][a][m]   4608
    float* val_sh = sh + 4608;        // [o][m][d]   9216
    float* c_sh   = sh + 13824;       // [o][m]      144
    float* at_sh  = sh + 13968;       // [o*64+nl][m] 9216 (scratch: wq stride-80)
    float* qh_sh  = sh + 23184;       // [nl][a] stride QSTRIDE

    const int t   = threadIdx.x;
    const int b   = blockIdx.y;
    const int n0  = blockIdx.x * 64;
    const int ob0 = b * O_;

    // ---- step 1: stage Wq[:, :D] into at_sh scratch; c into c_sh ----
    {
        // row a: 20 float4 (quarter q at f4 offset a*20 + q*5)
        const int a = t >> 4, j = t & 15;
        ((float4*)at_sh)[a * 20 + (j >> 2) * 5 + (j & 3)] =
            ((const float4*)Wq)[a * 24 + j];
        if (t < 144) c_sh[t] = g_c[(size_t)b * 144 + t];
    }
    __syncthreads();

    // ---- step 2: warps 0-7 compute qh (4 thr/n); warps 8-15 stage key/val ----
    if (t < 256) {
        const int nl = t >> 2;
        const int q  = t & 3;
        const float4* Hq = (const float4*)(H + ((size_t)b * NN + n0 + nl) * D_ + q * 16);
        ull hp[8];
        #pragma unroll
        for (int i = 0; i < 4; i++) {
            float4 v = Hq[i];
            hp[2 * i]     = pack2(v.x, v.y);
            hp[2 * i + 1] = pack2(v.z, v.w);
        }
        #pragma unroll
        for (int g = 0; g < 4; g++) {
            float qv[8];
            #pragma unroll
            for (int aa = 0; aa < 8; aa++) {
                const int a = g * 8 + aa;
                const ulonglong2* wr =
                    (const ulonglong2*)(at_sh + a * 80 + q * 20);
                ull acc = 0ull;
                #pragma unroll
                for (int j2 = 0; j2 < 4; j2++) {
                    ulonglong2 w = wr[j2];
                    acc = ffma2(hp[2 * j2],     w.x, acc);
                    acc = ffma2(hp[2 * j2 + 1], w.y, acc);
                }
                float2 f = unpack2(acc);
                float part = f.x + f.y;
                part += __shfl_xor_sync(0xffffffffu, part, 1);
                part += __shfl_xor_sync(0xffffffffu, part, 2);
                qv[aa] = part;
            }
            if (q == g) {
                *(float4*)(qh_sh + nl * QSTRIDE + g * 8) =
                    make_float4(qv[0], qv[1], qv[2], qv[3]);
                *(float4*)(qh_sh + nl * QSTRIDE + g * 8 + 4) =
                    make_float4(qv[4], qv[5], qv[6], qv[7]);
            }
        }
    } else {
        const int tt = t - 256;
        const float4* gk = (const float4*)(g_key + (size_t)ob0 * (A_ * M_));
        float4* k4 = (float4*)key_sh;
        for (int i = tt; i < 1152; i += 256) k4[i] = gk[i];
        const float4* gv = (const float4*)(g_val + (size_t)ob0 * (M_ * D_));
        float4* v4 = (float4*)val_sh;
        for (int i = tt; i < 2304; i += 256) v4[i] = gv[i];
    }
    __syncthreads();

    // ---- phase A: thread = (npair nl/nl+32, ol); lanes = (n1, n2) f32x2 ----
    if (t < 384) {
        const int nl = t & 31;
        const int ol = t >> 5;

        ull lg[M_];
        const float* cp = c_sh + ol * M_;
        #pragma unroll
        for (int m = 0; m < M_; m++) lg[m] = pack2(cp[m], cp[m]);

        const float* kp = key_sh + ol * (A_ * M_);
        const float4* qp1 = (const float4*)(qh_sh + nl * QSTRIDE);
        const float4* qp2 = (const float4*)(qh_sh + (nl + 32) * QSTRIDE);

        #pragma unroll
        for (int g = 0; g < 4; g++) {
            float q1r[8], q2r[8];
            { float4 v = qp1[2*g];   q1r[0]=v.x; q1r[1]=v.y; q1r[2]=v.z; q1r[3]=v.w; }
            { float4 v = qp1[2*g+1]; q1r[4]=v.x; q1r[5]=v.y; q1r[6]=v.z; q1r[7]=v.w; }
            { float4 v = qp2[2*g];   q2r[0]=v.x; q2r[1]=v.y; q2r[2]=v.z; q2r[3]=v.w; }
            { float4 v = qp2[2*g+1]; q2r[4]=v.x; q2r[5]=v.y; q2r[6]=v.z; q2r[7]=v.w; }
            #pragma unroll
            for (int aa = 0; aa < 8; aa++) {
                const int a = g * 8 + aa;
                const ull qq = pack2(q1r[aa], q2r[aa]);
                const ulonglong2* kr = (const ulonglong2*)(kp + a * M_);
                ulonglong2 K0 = kr[0], K1 = kr[1], K2 = kr[2];
                float2 f;
                f = unpack2(K0.x);
                lg[0]  = ffma2(qq, pack2(f.x, f.x), lg[0]);
                lg[1]  = ffma2(qq, pack2(f.y, f.y), lg[1]);
                f = unpack2(K0.y);
                lg[2]  = ffma2(qq, pack2(f.x, f.x), lg[2]);
                lg[3]  = ffma2(qq, pack2(f.y, f.y), lg[3]);
                f = unpack2(K1.x);
                lg[4]  = ffma2(qq, pack2(f.x, f.x), lg[4]);
                lg[5]  = ffma2(qq, pack2(f.y, f.y), lg[5]);
                f = unpack2(K1.y);
                lg[6]  = ffma2(qq, pack2(f.x, f.x), lg[6]);
                lg[7]  = ffma2(qq, pack2(f.y, f.y), lg[7]);
                f = unpack2(K2.x);
                lg[8]  = ffma2(qq, pack2(f.x, f.x), lg[8]);
                lg[9]  = ffma2(qq, pack2(f.y, f.y), lg[9]);
                f = unpack2(K2.y);
                lg[10] = ffma2(qq, pack2(f.x, f.x), lg[10]);
                lg[11] = ffma2(qq, pack2(f.y, f.y), lg[11]);
            }
        }

        float l1[M_], l2[M_];
        #pragma unroll
        for (int m = 0; m < M_; m++) {
            float2 f = unpack2(lg[m]);
            l1[m] = f.x; l2[m] = f.y;
        }
        // softmax n1
        {
            float mx = l1[0];
            #pragma unroll
            for (int m = 1; m < M_; m++) mx = fmaxf(mx, l1[m]);
            float ssum = 0.f, at[M_];
            #pragma unroll
            for (int m = 0; m < M_; m++) {
                const float e = __expf(l1[m] - mx);
                at[m] = e; ssum += e;
            }
            const float inv = __frcp_rn(ssum);
            #pragma unroll
            for (int m = 0; m < M_; m++) at[m] *= inv;
            float4* as = (float4*)(at_sh + (ol * 64 + nl) * M_);
            as[0] = make_float4(at[0], at[1], at[2],  at[3]);
            as[1] = make_float4(at[4], at[5], at[6],  at[7]);
            as[2] = make_float4(at[8], at[9], at[10], at[11]);
        }
        // softmax n2
        {
            float mx = l2[0];
            #pragma unroll
            for (int m = 1; m < M_; m++) mx = fmaxf(mx, l2[m]);
            float ssum = 0.f, at[M_];
            #pragma unroll
            for (int m = 0; m < M_; m++) {
                const float e = __expf(l2[m] - mx);
                at[m] = e; ssum += e;
            }
            const float inv = __frcp_rn(ssum);
            #pragma unroll
            for (int m = 0; m < M_; m++) at[m] *= inv;
            float4* as = (float4*)(at_sh + (ol * 64 + nl + 32) * M_);
            as[0] = make_float4(at[0], at[1], at[2],  at[3]);
            as[1] = make_float4(at[4], at[5], at[6],  at[7]);
            as[2] = make_float4(at[8], at[9], at[10], at[11]);
        }
    }
    __syncthreads();

    // ---- attn output: coalesced copy at_sh -> global (2304 f4 over 512 thr) ----
    for (int i = t; i < 2304; i += 512) {
        const int ol = i / 192, r = i - ol * 192;
        float4 v = ((const float4*)at_sh)[i];
        *(float4*)(out + ATT_OFF + ((size_t)(ob0 + ol) * NN + n0) * M_ + r * 4) = v;
    }

    // ---- phase B: thread = (dq2 8B-chunk, nn0 0..15); val hoisted per o ----
    const int dq2 = t & 31;
    const int nn0 = t >> 5;
    const ull ALPHA2 = pack2(0.1f, 0.1f);

    ull hh[4];
    #pragma unroll
    for (int p = 0; p < 4; p++)
        hh[p] = *(const ull*)(H + ((size_t)b * NN + n0 + p * 16 + nn0) * D_ + dq2 * 2);

    #pragma unroll 1
    for (int ol = 0; ol < O_; ol++) {
        ull vv[M_];
        const float* vb = val_sh + ol * (M_ * D_) + dq2 * 2;
        #pragma unroll
        for (int m = 0; m < M_; m++) vv[m] = *(const ull*)(vb + m * D_);

        const float* atb = at_sh + ol * 64 * M_;
        float* ob = out + ((size_t)(ob0 + ol) * NN + n0) * D_ + dq2 * 2;
        #pragma unroll
        for (int p = 0; p < 4; p++) {
            const int nn = p * 16 + nn0;
            const float4* ap = (const float4*)(atb + nn * M_);
            float4 u0 = ap[0], u1 = ap[1], u2 = ap[2];
            ull acc = 0ull;
            acc = ffma2(pack2(u0.x, u0.x), vv[0],  acc);
            acc = ffma2(pack2(u0.y, u0.y), vv[1],  acc);
            acc = ffma2(pack2(u0.z, u0.z), vv[2],  acc);
            acc = ffma2(pack2(u0.w, u0.w), vv[3],  acc);
            acc = ffma2(pack2(u1.x, u1.x), vv[4],  acc);
            acc = ffma2(pack2(u1.y, u1.y), vv[5],  acc);
            acc = ffma2(pack2(u1.z, u1.z), vv[6],  acc);
            acc = ffma2(pack2(u1.w, u1.w), vv[7],  acc);
            acc = ffma2(pack2(u2.x, u2.x), vv[8],  acc);
            acc = ffma2(pack2(u2.y, u2.y), vv[9],  acc);
            acc = ffma2(pack2(u2.z, u2.z), vv[10], acc);
            acc = ffma2(pack2(u2.w, u2.w), vv[11], acc);
            *(ull*)(ob + (size_t)nn * D_) = ffma2(acc, ALPHA2, hh[p]);
        }
    }
}

// ============================================================================
extern "C" void kernel_launch(void* const* d_in, const int* in_sizes, int n_in,
                              void* d_out, int out_size) {
    const float* H        = (const float*)d_in[0];
    const float* ts_out   = (const float*)d_in[1];
    const float* step_emb = (const float*)d_in[2];
    const float* key_emb  = (const float*)d_in[3];
    const float* val_emb  = (const float*)d_in[4];
    const float* Wk       = (const float*)d_in[5];
    const float* Wg       = (const float*)d_in[6];
    const float* bg       = (const float*)d_in[7];
    const float* Wq       = (const float*)d_in[8];
    const float* bq       = (const float*)d_in[9];
    float* out = (float*)d_out;

    precompute_kernel<<<dim3(O_, B_), 128>>>(ts_out, step_emb, key_emb, val_emb,
                                             Wk, Wg, bg, bq, Wq, out);

    const int smem_bytes = SMEM_FLOATS * 4;  // 101952 B
    cudaFuncSetAttribute(attn_kernel, cudaFuncAttributeMaxDynamicSharedMemorySize,
                         smem_bytes);
    attn_kernel<<<dim3(NN / 64, B_), 512, smem_bytes>>>(H, Wq, out);
}